// round 3
// baseline (speedup 1.0000x reference)
#include <cuda_runtime.h>
#include <cuda_bf16.h>
#include <cstdint>

// Problem constants (fixed by the reference)
#define CUBE_L   512
#define EQU_H    1024
#define EQU_W    2048
#define E_COUNT  4
#define CHANNELS 3
#define PLANE    (CUBE_L * CUBE_L)      // 262144

// Ordered non-coherent global load: asm volatile keeps program order among
// these loads, forcing ptxas to issue a whole batch before any consumer.
__device__ __forceinline__ float ldg_ordered(const float* p) {
    float v;
    asm volatile("ld.global.nc.f32 %0, [%1];" : "=f"(v) : "l"(p));
    return v;
}

// One thread per equirect pixel. Gathers are issued in two ordered batches of
// 24 (6 planes x 4 taps) to maximize memory-level parallelism per warp.
__global__ __launch_bounds__(256, 4) void cube2equirec_kernel(
    const float* __restrict__ x,        // (E*6, C, L, L)
    const float* __restrict__ uv,       // (H, W, 2)
    const int*   __restrict__ face_idx, // (H, W)
    float*       __restrict__ out)      // (E, C, H, W)
{
    const int p = blockIdx.x * blockDim.x + threadIdx.x;
    const int NPIX = EQU_H * EQU_W;

    // LUT loads (read exactly once -> streaming)
    const float2 uvp = __ldcs(reinterpret_cast<const float2*>(uv) + p);
    const int f = __ldcs(face_idx + p);

    const float u = uvp.x;
    const float v = uvp.y;

    int x0 = (int)floorf(u);
    int y0 = (int)floorf(v);
    x0 = min(max(x0, 0), CUBE_L - 1);
    y0 = min(max(y0, 0), CUBE_L - 1);
    const int x1 = min(x0 + 1, CUBE_L - 1);
    const int y1 = min(y0 + 1, CUBE_L - 1);

    const float wx = u - (float)x0;
    const float wy = v - (float)y0;
    const float w00 = (1.0f - wx) * (1.0f - wy);
    const float w01 = wx * (1.0f - wy);
    const float w10 = (1.0f - wx) * wy;
    const float w11 = wx * wy;

    const int o00 = y0 * CUBE_L + x0;
    const int o01 = y0 * CUBE_L + x1;
    const int o10 = y1 * CUBE_L + x0;
    const int o11 = y1 * CUBE_L + x1;

    // Per-face base (f is this thread's face); plane k = e*CHANNELS + c
    const float* fb = x + (size_t)f * CHANNELS * PLANE;

    // ---- Batch 1: planes 0..5 (e = 0,1), 24 ordered loads ----
    float g[24];
    #pragma unroll
    for (int k = 0; k < 6; ++k) {
        const int e = k / CHANNELS;
        const int c = k % CHANNELS;
        const float* b = fb + ((size_t)e * 6 * CHANNELS + c) * PLANE;
        g[4 * k + 0] = ldg_ordered(b + o00);
        g[4 * k + 1] = ldg_ordered(b + o01);
        g[4 * k + 2] = ldg_ordered(b + o10);
        g[4 * k + 3] = ldg_ordered(b + o11);
    }
    #pragma unroll
    for (int k = 0; k < 6; ++k) {
        const float val = g[4 * k + 0] * w00 + g[4 * k + 1] * w01 +
                          g[4 * k + 2] * w10 + g[4 * k + 3] * w11;
        __stcs(out + (size_t)k * NPIX + p, val);
    }

    // ---- Batch 2: planes 6..11 (e = 2,3), 24 ordered loads ----
    #pragma unroll
    for (int k = 0; k < 6; ++k) {
        const int e = 2 + k / CHANNELS;
        const int c = k % CHANNELS;
        const float* b = fb + ((size_t)e * 6 * CHANNELS + c) * PLANE;
        g[4 * k + 0] = ldg_ordered(b + o00);
        g[4 * k + 1] = ldg_ordered(b + o01);
        g[4 * k + 2] = ldg_ordered(b + o10);
        g[4 * k + 3] = ldg_ordered(b + o11);
    }
    #pragma unroll
    for (int k = 0; k < 6; ++k) {
        const float val = g[4 * k + 0] * w00 + g[4 * k + 1] * w01 +
                          g[4 * k + 2] * w10 + g[4 * k + 3] * w11;
        __stcs(out + (size_t)(k + 6) * NPIX + p, val);
    }
}

extern "C" void kernel_launch(void* const* d_in, const int* in_sizes, int n_in,
                              void* d_out, int out_size)
{
    const float* x        = (const float*)d_in[0];
    const float* uv       = (const float*)d_in[1];
    const int*   face_idx = (const int*)d_in[2];
    float*       out      = (float*)d_out;

    const int npix = EQU_H * EQU_W;          // 2'097'152, divisible by 256
    const int threads = 256;
    const int blocks = npix / threads;
    cube2equirec_kernel<<<blocks, threads>>>(x, uv, face_idx, out);
}